// round 11
// baseline (speedup 1.0000x reference)
#include <cuda_runtime.h>
#include <cuda_bf16.h>
#include <cstdint>

#define NB_B 4096
#define ND 16
#define NM 4
#define NR 2048
#define NC 10
#define NDP1 17
#define MU 8.5f

typedef unsigned long long ull;

// cons planes, mean-centered bf16x2, pair-interleaved for LDG.128:
//   g_consA[q] = {p0/even, p0/odd, p1/even, p1/odd}
//   g_consB[q] = {p2/even, p2/odd, p3/even, p3/odd}
//   g_consC[q] = {p4/even, p4/odd}
__device__ uint4    g_consA[NR / 2];
__device__ uint4    g_consB[NR / 2];
__device__ uint2    g_consC[NR / 2];
__device__ unsigned g_rpack[NR];                        // 16 dims x 2 bits
__device__ float    g_norm_scratch[(size_t)NB_B * NR];  // fallback only

__device__ __forceinline__ ull pack2(float x, float y) {
    ull r;
    asm("mov.b64 %0, {%1, %2};" : "=l"(r) : "f"(x), "f"(y));
    return r;
}
__device__ __forceinline__ void unpack2(float& x, float& y, ull v) {
    asm("mov.b64 {%0, %1}, %2;" : "=f"(x), "=f"(y) : "l"(v));
}
__device__ __forceinline__ void ffma2(ull& d, ull a, ull b) {
    asm("fma.rn.f32x2 %0, %1, %2, %0;" : "+l"(d) : "l"(a), "l"(b));
}
__device__ __forceinline__ ull fmul2(ull a, ull b) {
    ull r;
    asm("mul.rn.f32x2 %0, %1, %2;" : "=l"(r) : "l"(a), "l"(b));
    return r;
}

// ---------------------------------------------------------------------------
// K0: coalesced prep. 128 blocks x 256 thr; 16 rules/block (R10-proven).
// ---------------------------------------------------------------------------
__global__ __launch_bounds__(256) void prep_kernel(
    const float* __restrict__ cons, const int* __restrict__ rules) {
    __shared__ float sc[16 * NDP1 * NC];   // 10880 B
    __shared__ int   sr[16 * ND];

    const int tid = threadIdx.x;
    const int r0  = blockIdx.x * 16;

    const float* cbase = cons + (size_t)r0 * NDP1 * NC;
#pragma unroll
    for (int i = tid; i < 16 * NDP1 * NC; i += 256) sc[i] = cbase[i];
    sr[tid] = rules[r0 * ND + tid];        // exactly 256 ints
    __syncthreads();

    if (tid < 80) {
        const int rl = tid / 5, p = tid % 5;
        const float* row = sc + rl * NDP1 * NC + 2 * p;
        float s0 = 0.f, s1 = 0.f;
#pragma unroll
        for (int j = 0; j < NDP1; ++j) {
            s0 += row[j * NC];
            s1 += row[j * NC + 1];
        }
        const int gw = r0 + rl, q = gw >> 1, r1 = gw & 1;
        __nv_bfloat162 h = __floats2bfloat162_rn(s0 - MU, s1 - MU);
        unsigned wb = *(unsigned*)&h;
        if (p == 0)      ((unsigned*)g_consA)[q * 4 + 0 + r1] = wb;
        else if (p == 1) ((unsigned*)g_consA)[q * 4 + 2 + r1] = wb;
        else if (p == 2) ((unsigned*)g_consB)[q * 4 + 0 + r1] = wb;
        else if (p == 3) ((unsigned*)g_consB)[q * 4 + 2 + r1] = wb;
        else             ((unsigned*)g_consC)[q * 2 + r1]     = wb;
    } else if (tid < 96) {
        const int rl = tid - 80;
        unsigned pk = 0;
#pragma unroll
        for (int d = 0; d < ND; ++d)
            pk |= ((unsigned)sr[rl * ND + d] & 3u) << (2 * d);
        g_rpack[r0 + rl] = pk;
    }
}

// ---------------------------------------------------------------------------
// K1 (fused): block = 8 warps = 2 batch-pairs x 4 warps; 8 k-iters/warp.
// PASS 1 (low regs): table lookups + exp + park unnormalized packed f in
// smem + running sums. PASS 2: reload own parked f, scale by inv (packed),
// STG normalized, and do the GEMV there (accumulators born+die in pass 2).
// Peak regs < 51 -> 5 blocks/SM.
// ---------------------------------------------------------------------------
__global__ __launch_bounds__(256, 5) void fused_kernel(
    const float* __restrict__ x,
    const float* __restrict__ centers,
    const float* __restrict__ widths,
    float* __restrict__ norm_out,
    float* __restrict__ xext_out,
    float* __restrict__ out,
    int write_xext) {
    __shared__ ull    s_f[2][2][NR / 2];  // [pair-group][half][q] : 32 KB
    __shared__ float  s_e[4][64];
    __shared__ float2 s_tab[2][8][16];    // [pair][table][idx] = (eA, eB)
    __shared__ float  s_sum[8][2];
    __shared__ float  s_acc[8][2][NC];
    __shared__ float  s_sx[4];

    const int tid  = threadIdx.x;
    const int w    = tid >> 5;
    const int lane = tid & 31;
    const int g    = w >> 2;        // batch-pair group (0/1)
    const int qw   = w & 3;         // quarter within group
    const int bbase = blockIdx.x * 4;

    // setup: warps 0..3 each handle batch bbase+w (pair = w>>1, half = w&1)
    if (w < 4) {
        const int b = bbase + w;
        float xv = (lane < ND) ? x[b * ND + lane] : 0.f;
        float sx = xv;
#pragma unroll
        for (int off = 16; off > 0; off >>= 1)
            sx += __shfl_xor_sync(0xffffffffu, sx, off);
        sx += 1.f;
        if (lane == 0) s_sx[w] = sx;
        if (write_xext) {
            if (lane < ND) xext_out[b * NDP1 + lane] = xv;
            if (lane == ND) xext_out[b * NDP1 + ND] = 1.f;
        }
#pragma unroll
        for (int k = lane; k < 64; k += 32) {
            int d = k >> 2, m = k & 3;
            float c  = centers[d * NM + m];
            float wd = widths[d * NM + m];
            float xd = __shfl_sync(0xffffffffu, xv, d);
            float dx = xd - c;
            s_e[w][k] = -(dx * dx) / (2.f * wd * wd);
        }
        __syncwarp();
        const int pr = w >> 1, h = w & 1;
#pragma unroll
        for (int k = lane; k < 128; k += 32) {
            int t = k >> 4, i = k & 15;
            float v = s_e[w][(2 * t) * 4 + (i & 3)] +
                      s_e[w][(2 * t + 1) * 4 + (i >> 2)];
            if (h == 0) s_tab[pr][t][i].x = v;
            else        s_tab[pr][t][i].y = v;
        }
    }
    __syncthreads();

    const float2 (*tab)[16] = s_tab[g];
    const uint2* __restrict__ rp = (const uint2*)g_rpack;

    // ---- PASS 1: lookups, exp, park f, sums (no accumulators) ----
    float sumA = 0.f, sumB = 0.f;
#pragma unroll
    for (int k = 0; k < 8; ++k) {
        const int q = (qw * 8 + k) * 32 + lane;   // rule-pair index
        uint2 pp = rp[q];
        float2 v0 = tab[0][pp.x & 15];
        float2 v1 = tab[0][pp.y & 15];
        float s0A = v0.x, s0B = v0.y, s1A = v1.x, s1B = v1.y;
#pragma unroll
        for (int t = 1; t < 8; ++t) {
            float2 a = tab[t][(pp.x >> (4 * t)) & 15];
            float2 b2 = tab[t][(pp.y >> (4 * t)) & 15];
            s0A += a.x;  s0B += a.y;
            s1A += b2.x; s1B += b2.y;
        }
        float f0A = __expf(s0A), f1A = __expf(s1A);
        float f0B = __expf(s0B), f1B = __expf(s1B);
        sumA += f0A + f1A;
        sumB += f0B + f1B;
        s_f[g][0][q] = pack2(f0A, f1A);           // park unnormalized f
        s_f[g][1][q] = pack2(f0B, f1B);
    }

#pragma unroll
    for (int off = 16; off > 0; off >>= 1) {
        sumA += __shfl_xor_sync(0xffffffffu, sumA, off);
        sumB += __shfl_xor_sync(0xffffffffu, sumB, off);
    }
    if (lane == 0) { s_sum[w][0] = sumA; s_sum[w][1] = sumB; }
    __syncthreads();

    const float totA = s_sum[g * 4][0] + s_sum[g * 4 + 1][0] +
                       s_sum[g * 4 + 2][0] + s_sum[g * 4 + 3][0];
    const float totB = s_sum[g * 4][1] + s_sum[g * 4 + 1][1] +
                       s_sum[g * 4 + 2][1] + s_sum[g * 4 + 3][1];
    const float invA = 1.f / (totA + 1e-9f);
    const float invB = 1.f / (totB + 1e-9f);
    const ull invA2 = pack2(invA, invA);
    const ull invB2 = pack2(invB, invB);

    // ---- PASS 2: normalize + STG + GEMV (accs live only here) ----
    const int bA = bbase + g * 2, bB = bA + 1;
    ull* npA = (ull*)(norm_out + (size_t)bA * NR);
    ull* npB = (ull*)(norm_out + (size_t)bB * NR);

    ull accA[5], accB[5];                 // packed (c=2p, c=2p+1)
#pragma unroll
    for (int p = 0; p < 5; ++p) { accA[p] = 0ull; accB[p] = 0ull; }

#pragma unroll
    for (int k = 0; k < 8; ++k) {
        const int q = (qw * 8 + k) * 32 + lane;
        const ull fnA = fmul2(s_f[g][0][q], invA2);   // (fn_even, fn_odd)
        const ull fnB = fmul2(s_f[g][1][q], invB2);
        npA[q] = fnA;                                 // normalized norm_fs
        npB[q] = fnB;

        float feA, foA, feB, foB;
        unpack2(feA, foA, fnA);
        unpack2(feB, foB, fnB);
        const ull f0A2 = pack2(feA, feA), f1A2 = pack2(foA, foA);
        const ull f0B2 = pack2(feB, feB), f1B2 = pack2(foB, foB);

        uint4 cA = g_consA[q];
        uint4 cB = g_consB[q];
        uint2 cC = g_consC[q];
        const unsigned we[5] = {cA.x, cA.z, cB.x, cB.z, cC.x};
        const unsigned wo[5] = {cA.y, cA.w, cB.y, cB.w, cC.y};
#pragma unroll
        for (int p = 0; p < 5; ++p) {
            ull ce = pack2(__uint_as_float(we[p] << 16),
                           __uint_as_float(we[p] & 0xffff0000u));
            ull co = pack2(__uint_as_float(wo[p] << 16),
                           __uint_as_float(wo[p] & 0xffff0000u));
            ffma2(accA[p], f0A2, ce);
            ffma2(accA[p], f1A2, co);
            ffma2(accB[p], f0B2, ce);
            ffma2(accB[p], f1B2, co);
        }
    }

    float rA[NC], rB[NC];
#pragma unroll
    for (int p = 0; p < 5; ++p) {
        unpack2(rA[2 * p], rA[2 * p + 1], accA[p]);
        unpack2(rB[2 * p], rB[2 * p + 1], accB[p]);
    }
#pragma unroll
    for (int off = 16; off > 0; off >>= 1)
#pragma unroll
        for (int c = 0; c < NC; ++c) {
            rA[c] += __shfl_xor_sync(0xffffffffu, rA[c], off);
            rB[c] += __shfl_xor_sync(0xffffffffu, rB[c], off);
        }
    if (lane == 0) {
#pragma unroll
        for (int c = 0; c < NC; ++c) {
            s_acc[w][0][c] = rA[c];
            s_acc[w][1][c] = rB[c];
        }
    }
    __syncthreads();

    // ---- output: acc is already normalized (fn), so add MU*tot*inv ----
    if (tid < 40) {
        const int gg = tid / 20, h = (tid / 10) % 2, c = tid % 10;
        float a = s_acc[gg * 4][h][c] + s_acc[gg * 4 + 1][h][c] +
                  s_acc[gg * 4 + 2][h][c] + s_acc[gg * 4 + 3][h][c];
        float tot = s_sum[gg * 4][h] + s_sum[gg * 4 + 1][h] +
                    s_sum[gg * 4 + 2][h] + s_sum[gg * 4 + 3][h];
        float inv = 1.f / (tot + 1e-9f);
        const int b = bbase + gg * 2 + h;
        out[(size_t)b * NC + c] = (a + MU * tot * inv) * s_sx[gg * 2 + h];
    }
}

// ---------------------------------------------------------------------------
extern "C" void kernel_launch(void* const* d_in, const int* in_sizes, int n_in,
                              void* d_out, int out_size) {
    const float* x       = (const float*)d_in[0];
    const float* centers = (const float*)d_in[1];
    const float* widths  = (const float*)d_in[2];
    const float* cons    = (const float*)d_in[3];
    const int*   rules   = (const int*)d_in[4];
    float* out = (float*)d_out;

    const long long TOTAL = (long long)NB_B * NC + (long long)NB_B * NR +
                            (long long)NB_B * NDP1;

    float* out_p = out;
    float* norm_p;
    float* xext_p = out;
    int write_xext = 0;

    if ((long long)out_size == TOTAL) {
        norm_p = out + (size_t)NB_B * NC;
        xext_p = out + (size_t)NB_B * NC + (size_t)NB_B * NR;
        write_xext = 1;
    } else {
        void* sp = nullptr;
        cudaGetSymbolAddress(&sp, g_norm_scratch);
        norm_p = (float*)sp;
    }

    prep_kernel<<<NR / 16, 256>>>(cons, rules);
    fused_kernel<<<NB_B / 4, 256>>>(x, centers, widths, norm_p,
                                    xext_p, out_p, write_xext);
}

// round 12
// speedup vs baseline: 1.0011x; 1.0011x over previous
#include <cuda_runtime.h>
#include <cuda_bf16.h>
#include <cstdint>

#define NB_B 4096
#define ND 16
#define NM 4
#define NR 2048
#define NC 10
#define NDP1 17
#define MU 8.5f

typedef unsigned long long ull;

// cons planes, mean-centered bf16x2, pair-interleaved for LDG.128:
//   g_consA[q] = {p0/even, p0/odd, p1/even, p1/odd}
//   g_consB[q] = {p2/even, p2/odd, p3/even, p3/odd}
//   g_consC[q] = {p4/even, p4/odd}
__device__ uint4    g_consA[NR / 2];
__device__ uint4    g_consB[NR / 2];
__device__ uint2    g_consC[NR / 2];
__device__ unsigned g_rpack[NR];                        // 16 dims x 2 bits
__device__ float    g_norm_scratch[(size_t)NB_B * NR];  // fallback only

__device__ __forceinline__ ull pack2(float x, float y) {
    ull r;
    asm("mov.b64 %0, {%1, %2};" : "=l"(r) : "f"(x), "f"(y));
    return r;
}
__device__ __forceinline__ void unpack2(float& x, float& y, ull v) {
    asm("mov.b64 {%0, %1}, %2;" : "=f"(x), "=f"(y) : "l"(v));
}
__device__ __forceinline__ void ffma2(ull& d, ull a, ull b) {
    asm("fma.rn.f32x2 %0, %1, %2, %0;" : "+l"(d) : "l"(a), "l"(b));
}
__device__ __forceinline__ ull fmul2(ull a, ull b) {
    ull r;
    asm("mul.rn.f32x2 %0, %1, %2;" : "=l"(r) : "l"(a), "l"(b));
    return r;
}

// sum of 8 batch-paired table entries selected by the 16 2-bit fields of u
__device__ __forceinline__ float2 lookup8(const float2 (*tab)[16], unsigned u) {
    float2 r = tab[0][u & 15];
#pragma unroll
    for (int t = 1; t < 8; ++t) {
        float2 a = tab[t][(u >> (4 * t)) & 15];
        r.x += a.x;
        r.y += a.y;
    }
    return r;
}

// ---------------------------------------------------------------------------
// K0: coalesced prep. 128 blocks x 256 thr; 16 rules/block (R10-proven).
// ---------------------------------------------------------------------------
__global__ __launch_bounds__(256) void prep_kernel(
    const float* __restrict__ cons, const int* __restrict__ rules) {
    __shared__ float sc[16 * NDP1 * NC];   // 10880 B
    __shared__ int   sr[16 * ND];

    const int tid = threadIdx.x;
    const int r0  = blockIdx.x * 16;

    const float* cbase = cons + (size_t)r0 * NDP1 * NC;
#pragma unroll
    for (int i = tid; i < 16 * NDP1 * NC; i += 256) sc[i] = cbase[i];
    sr[tid] = rules[r0 * ND + tid];        // exactly 256 ints
    __syncthreads();

    if (tid < 80) {
        const int rl = tid / 5, p = tid % 5;
        const float* row = sc + rl * NDP1 * NC + 2 * p;
        float s0 = 0.f, s1 = 0.f;
#pragma unroll
        for (int j = 0; j < NDP1; ++j) {
            s0 += row[j * NC];
            s1 += row[j * NC + 1];
        }
        const int gw = r0 + rl, q = gw >> 1, r1 = gw & 1;
        __nv_bfloat162 h = __floats2bfloat162_rn(s0 - MU, s1 - MU);
        unsigned wb = *(unsigned*)&h;
        if (p == 0)      ((unsigned*)g_consA)[q * 4 + 0 + r1] = wb;
        else if (p == 1) ((unsigned*)g_consA)[q * 4 + 2 + r1] = wb;
        else if (p == 2) ((unsigned*)g_consB)[q * 4 + 0 + r1] = wb;
        else if (p == 3) ((unsigned*)g_consB)[q * 4 + 2 + r1] = wb;
        else             ((unsigned*)g_consC)[q * 2 + r1]     = wb;
    } else if (tid < 96) {
        const int rl = tid - 80;
        unsigned pk = 0;
#pragma unroll
        for (int d = 0; d < ND; ++d)
            pk |= ((unsigned)sr[rl * ND + d] & 3u) << (2 * d);
        g_rpack[r0 + rl] = pk;
    }
}

// ---------------------------------------------------------------------------
// K1 (fused): 128 thr = 4 warps = ONE batch-pair. Lane owns 2 adjacent
// rule-pairs per iteration -> all memory ops are .128:
//   rpack LDG.128, f-park STS.128/LDS.128, norm STG.128, consC LDG.128.
// PASS 1: lookups + exp + park f + sums. PASS 2: normalize + STG + GEMV.
// ---------------------------------------------------------------------------
__global__ __launch_bounds__(128, 9) void fused_kernel(
    const float* __restrict__ x,
    const float* __restrict__ centers,
    const float* __restrict__ widths,
    float* __restrict__ norm_out,
    float* __restrict__ xext_out,
    float* __restrict__ out,
    int write_xext) {
    __shared__ __align__(16) ull s_f[2][NR / 2];  // [half][q] : 16 KB
    __shared__ float  s_e[2][64];
    __shared__ float2 s_tab[8][16];               // [table][idx] = (eA, eB)
    __shared__ float  s_sum[4][2];
    __shared__ float  s_acc[4][2][NC];
    __shared__ float  s_sx[2];

    const int tid  = threadIdx.x;
    const int w    = tid >> 5;
    const int lane = tid & 31;
    const int bA   = blockIdx.x * 2;
    const int bB   = bA + 1;

    // setup: warps 0,1 build per-batch tables (warp h -> component h)
    if (w < 2) {
        const int b = bA + w;
        float xv = (lane < ND) ? x[b * ND + lane] : 0.f;
        float sx = xv;
#pragma unroll
        for (int off = 16; off > 0; off >>= 1)
            sx += __shfl_xor_sync(0xffffffffu, sx, off);
        sx += 1.f;
        if (lane == 0) s_sx[w] = sx;
        if (write_xext) {
            if (lane < ND) xext_out[b * NDP1 + lane] = xv;
            if (lane == ND) xext_out[b * NDP1 + ND] = 1.f;
        }
#pragma unroll
        for (int k = lane; k < 64; k += 32) {
            int d = k >> 2, m = k & 3;
            float c  = centers[d * NM + m];
            float wd = widths[d * NM + m];
            float xd = __shfl_sync(0xffffffffu, xv, d);
            float dx = xd - c;
            s_e[w][k] = -(dx * dx) / (2.f * wd * wd);
        }
        __syncwarp();
#pragma unroll
        for (int k = lane; k < 128; k += 32) {
            int t = k >> 4, i = k & 15;
            float v = s_e[w][(2 * t) * 4 + (i & 3)] +
                      s_e[w][(2 * t + 1) * 4 + (i >> 2)];
            if (w == 0) s_tab[t][i].x = v;
            else        s_tab[t][i].y = v;
        }
    }
    __syncthreads();

    // ---- PASS 1: lookups, exp, park f (STS.128), sums ----
    float sumA = 0.f, sumB = 0.f;
#pragma unroll
    for (int kk = 0; kk < 4; ++kk) {
        const int q2 = (w * 4 + kk) * 64 + lane * 2;      // even pair index
        uint4 pp = ((const uint4*)g_rpack)[q2 >> 1];      // rules 2q2..2q2+3
        float2 s0 = lookup8(s_tab, pp.x);
        float2 s1 = lookup8(s_tab, pp.y);
        float2 s2 = lookup8(s_tab, pp.z);
        float2 s3 = lookup8(s_tab, pp.w);
        float f0A = __expf(s0.x), f1A = __expf(s1.x);
        float f2A = __expf(s2.x), f3A = __expf(s3.x);
        float f0B = __expf(s0.y), f1B = __expf(s1.y);
        float f2B = __expf(s2.y), f3B = __expf(s3.y);
        sumA += (f0A + f1A) + (f2A + f3A);
        sumB += (f0B + f1B) + (f2B + f3B);
        ulonglong2 pA, pB;
        pA.x = pack2(f0A, f1A); pA.y = pack2(f2A, f3A);
        pB.x = pack2(f0B, f1B); pB.y = pack2(f2B, f3B);
        *(ulonglong2*)&s_f[0][q2] = pA;                   // STS.128
        *(ulonglong2*)&s_f[1][q2] = pB;
    }

#pragma unroll
    for (int off = 16; off > 0; off >>= 1) {
        sumA += __shfl_xor_sync(0xffffffffu, sumA, off);
        sumB += __shfl_xor_sync(0xffffffffu, sumB, off);
    }
    if (lane == 0) { s_sum[w][0] = sumA; s_sum[w][1] = sumB; }
    __syncthreads();

    const float totA = s_sum[0][0] + s_sum[1][0] + s_sum[2][0] + s_sum[3][0];
    const float totB = s_sum[0][1] + s_sum[1][1] + s_sum[2][1] + s_sum[3][1];
    const float invA = 1.f / (totA + 1e-9f);
    const float invB = 1.f / (totB + 1e-9f);
    const ull invA2 = pack2(invA, invA);
    const ull invB2 = pack2(invB, invB);

    // ---- PASS 2: normalize (LDS.128 -> STG.128) + GEMV ----
    ulonglong2* npA = (ulonglong2*)(norm_out + (size_t)bA * NR);
    ulonglong2* npB = (ulonglong2*)(norm_out + (size_t)bB * NR);

    ull accA[5], accB[5];                 // packed (c=2p, c=2p+1)
#pragma unroll
    for (int p = 0; p < 5; ++p) { accA[p] = 0ull; accB[p] = 0ull; }

#pragma unroll
    for (int kk = 0; kk < 4; ++kk) {
        const int q2 = (w * 4 + kk) * 64 + lane * 2;
        ulonglong2 fA = *(const ulonglong2*)&s_f[0][q2];  // LDS.128
        ulonglong2 fB = *(const ulonglong2*)&s_f[1][q2];
        ulonglong2 nA, nB;
        nA.x = fmul2(fA.x, invA2); nA.y = fmul2(fA.y, invA2);
        nB.x = fmul2(fB.x, invB2); nB.y = fmul2(fB.y, invB2);
        npA[q2 >> 1] = nA;                                // STG.128
        npB[q2 >> 1] = nB;

        uint4 c0 = g_consA[q2];
        uint4 c1 = g_consA[q2 + 1];
        uint4 c2 = g_consB[q2];
        uint4 c3 = g_consB[q2 + 1];
        uint4 cc = ((const uint4*)g_consC)[q2 >> 1];      // consC pair

        float e0A, o0A, e1A, o1A, e0B, o0B, e1B, o1B;
        unpack2(e0A, o0A, nA.x);  // pair q2   batch A (even, odd rule)
        unpack2(e1A, o1A, nA.y);  // pair q2+1 batch A
        unpack2(e0B, o0B, nB.x);
        unpack2(e1B, o1B, nB.y);
        const ull e0A2 = pack2(e0A, e0A), o0A2 = pack2(o0A, o0A);
        const ull e1A2 = pack2(e1A, e1A), o1A2 = pack2(o1A, o1A);
        const ull e0B2 = pack2(e0B, e0B), o0B2 = pack2(o0B, o0B);
        const ull e1B2 = pack2(e1B, e1B), o1B2 = pack2(o1B, o1B);

        const unsigned we0[5] = {c0.x, c0.z, c2.x, c2.z, cc.x};
        const unsigned wo0[5] = {c0.y, c0.w, c2.y, c2.w, cc.y};
        const unsigned we1[5] = {c1.x, c1.z, c3.x, c3.z, cc.z};
        const unsigned wo1[5] = {c1.y, c1.w, c3.y, c3.w, cc.w};
#pragma unroll
        for (int p = 0; p < 5; ++p) {
            ull ce0 = pack2(__uint_as_float(we0[p] << 16),
                            __uint_as_float(we0[p] & 0xffff0000u));
            ull co0 = pack2(__uint_as_float(wo0[p] << 16),
                            __uint_as_float(wo0[p] & 0xffff0000u));
            ull ce1 = pack2(__uint_as_float(we1[p] << 16),
                            __uint_as_float(we1[p] & 0xffff0000u));
            ull co1 = pack2(__uint_as_float(wo1[p] << 16),
                            __uint_as_float(wo1[p] & 0xffff0000u));
            ffma2(accA[p], e0A2, ce0);
            ffma2(accA[p], o0A2, co0);
            ffma2(accA[p], e1A2, ce1);
            ffma2(accA[p], o1A2, co1);
            ffma2(accB[p], e0B2, ce0);
            ffma2(accB[p], o0B2, co0);
            ffma2(accB[p], e1B2, ce1);
            ffma2(accB[p], o1B2, co1);
        }
    }

    float rA[NC], rB[NC];
#pragma unroll
    for (int p = 0; p < 5; ++p) {
        unpack2(rA[2 * p], rA[2 * p + 1], accA[p]);
        unpack2(rB[2 * p], rB[2 * p + 1], accB[p]);
    }
#pragma unroll
    for (int off = 16; off > 0; off >>= 1)
#pragma unroll
        for (int c = 0; c < NC; ++c) {
            rA[c] += __shfl_xor_sync(0xffffffffu, rA[c], off);
            rB[c] += __shfl_xor_sync(0xffffffffu, rB[c], off);
        }
    if (lane == 0) {
#pragma unroll
        for (int c = 0; c < NC; ++c) {
            s_acc[w][0][c] = rA[c];
            s_acc[w][1][c] = rB[c];
        }
    }
    __syncthreads();

    // ---- output: acc is normalized (fn), add MU*tot*inv, scale by sx ----
    if (tid < 20) {
        const int h = tid / 10, c = tid % 10;
        float a = s_acc[0][h][c] + s_acc[1][h][c] +
                  s_acc[2][h][c] + s_acc[3][h][c];
        float tot = h ? totB : totA;
        float inv = h ? invB : invA;
        out[(size_t)(bA + h) * NC + c] = (a + MU * tot * inv) * s_sx[h];
    }
}

// ---------------------------------------------------------------------------
extern "C" void kernel_launch(void* const* d_in, const int* in_sizes, int n_in,
                              void* d_out, int out_size) {
    const float* x       = (const float*)d_in[0];
    const float* centers = (const float*)d_in[1];
    const float* widths  = (const float*)d_in[2];
    const float* cons    = (const float*)d_in[3];
    const int*   rules   = (const int*)d_in[4];
    float* out = (float*)d_out;

    const long long TOTAL = (long long)NB_B * NC + (long long)NB_B * NR +
                            (long long)NB_B * NDP1;

    float* out_p = out;
    float* norm_p;
    float* xext_p = out;
    int write_xext = 0;

    if ((long long)out_size == TOTAL) {
        norm_p = out + (size_t)NB_B * NC;
        xext_p = out + (size_t)NB_B * NC + (size_t)NB_B * NR;
        write_xext = 1;
    } else {
        void* sp = nullptr;
        cudaGetSymbolAddress(&sp, g_norm_scratch);
        norm_p = (float*)sp;
    }

    prep_kernel<<<NR / 16, 256>>>(cons, rules);
    fused_kernel<<<NB_B / 2, 128>>>(x, centers, widths, norm_p,
                                    xext_p, out_p, write_xext);
}